// round 2
// baseline (speedup 1.0000x reference)
#include <cuda_runtime.h>

// ---------------------------------------------------------------------------
// Problem constants
// ---------------------------------------------------------------------------
#define TOK   8192      // B*S tokens
#define DIMN  512       // ATTN_DIM
#define SEQ   512
#define NBAT  16
#define NHEAD 8
#define FFD   2048
#define CBSZ  8192
#define CBD   64
#define NSPLIT 4        // VQ codebook splits

// ---------------------------------------------------------------------------
// Device scratch
// ---------------------------------------------------------------------------
__device__ float g_h  [TOK * DIMN];
__device__ float g_lnb[TOK * DIMN];
__device__ float g_qb [TOK * DIMN];
__device__ float g_kb [TOK * DIMN];
__device__ float g_vb [TOK * DIMN];
__device__ float g_att[TOK * DIMN];
__device__ float g_ffb[TOK * FFD];
__device__ float g_z  [TOK * CBD];
__device__ float g_cn [CBSZ];
__device__ float g_bv [NSPLIT][TOK];
__device__ int   g_bc [NSPLIT][TOK];
__device__ int   g_idx[TOK];
__device__ float g_part[NBAT];

// ---------------------------------------------------------------------------
// Helpers
// ---------------------------------------------------------------------------
enum { EPI_NONE = 0, EPI_BIAS = 1, EPI_BIAS_POS = 2, EPI_RES = 3,
       EPI_RES_BIAS = 4, EPI_GELU_BIAS = 5 };

__device__ __forceinline__ float gelu_f(float x) {
    float x3 = x * x * x;
    float t  = tanhf(0.7978845608028654f * (x + 0.044715f * x3));
    return 0.5f * x * (1.0f + t);
}

__device__ __forceinline__ void fma2(unsigned long long& d,
                                     unsigned long long a,
                                     unsigned long long b) {
    asm("fma.rn.f32x2 %0, %1, %2, %0;" : "+l"(d) : "l"(a), "l"(b));
}
__device__ __forceinline__ float2 unpack2(unsigned long long v) {
    float2 r;
    asm("mov.b64 {%0, %1}, %2;" : "=f"(r.x), "=f"(r.y) : "l"(v));
    return r;
}

// ---------------------------------------------------------------------------
// SGEMM: C[M,N] = A[M,K] @ B[K,N] (+epilogue). M multiple of 128.
// 128x128 tile, BK=16, double-buffered smem, A stored DUPLICATED in smem so
// the inner loop is pure LDS.128 + fma.f32x2 (no per-kk dup movs).
// ---------------------------------------------------------------------------
__global__ __launch_bounds__(256, 2)
void sgemm_k(const float* __restrict__ A, const float* __restrict__ B,
             float* __restrict__ C, const float* __restrict__ bias,
             const float* __restrict__ extra, int N, int K, int epi)
{
    __shared__ float As[2][16][256];   // logical row r duplicated at 2r, 2r+1
    __shared__ float Bs[2][16][128];
    const int tid  = threadIdx.x;
    const int row0 = blockIdx.y * 128;
    const int col0 = blockIdx.x * 128;
    const int trow = tid >> 4;
    const int tcol = tid & 15;

    // loader indices
    const int ar  = (tid << 1) >> 3;            // placeholder (recomputed below)
    (void)ar;

    unsigned long long acc[8][4];
#pragma unroll
    for (int i = 0; i < 8; i++)
#pragma unroll
        for (int j = 0; j < 4; j++) acc[i][j] = 0ULL;

    float4 pa[2], pb[2];
    // ---- load tile 0 into regs ----
#pragma unroll
    for (int v = 0; v < 2; v++) {
        int idx = tid + v * 256;
        int r  = idx >> 2, kq = (idx & 3) << 2;
        pa[v] = *(const float4*)(A + (long long)(row0 + r) * K + kq);
        int rb = idx >> 5, cb = (idx & 31) << 2;
        pb[v] = make_float4(0.f, 0.f, 0.f, 0.f);
        if (col0 + cb < N)
            pb[v] = *(const float4*)(B + (long long)rb * N + (col0 + cb));
    }
    // ---- store tile 0 into buf 0 ----
#pragma unroll
    for (int v = 0; v < 2; v++) {
        int idx = tid + v * 256;
        int r  = idx >> 2, kq = (idx & 3) << 2;
        *(float2*)(&As[0][kq + 0][2 * r]) = make_float2(pa[v].x, pa[v].x);
        *(float2*)(&As[0][kq + 1][2 * r]) = make_float2(pa[v].y, pa[v].y);
        *(float2*)(&As[0][kq + 2][2 * r]) = make_float2(pa[v].z, pa[v].z);
        *(float2*)(&As[0][kq + 3][2 * r]) = make_float2(pa[v].w, pa[v].w);
        int rb = idx >> 5, cb = (idx & 31) << 2;
        *(float4*)(&Bs[0][rb][cb]) = pb[v];
    }
    __syncthreads();

    const int nt = K >> 4;
    for (int t = 0; t < nt; t++) {
        const int p = t & 1;
        if (t + 1 < nt) {
            int k0 = (t + 1) << 4;
#pragma unroll
            for (int v = 0; v < 2; v++) {
                int idx = tid + v * 256;
                int r  = idx >> 2, kq = (idx & 3) << 2;
                pa[v] = *(const float4*)(A + (long long)(row0 + r) * K + (k0 + kq));
                int rb = idx >> 5, cb = (idx & 31) << 2;
                pb[v] = make_float4(0.f, 0.f, 0.f, 0.f);
                if (col0 + cb < N)
                    pb[v] = *(const float4*)(B + (long long)(k0 + rb) * N + (col0 + cb));
            }
        }
#pragma unroll
        for (int kk = 0; kk < 16; kk++) {
            const float* arow = &As[p][kk][trow * 16];
            const float* brow = &Bs[p][kk][tcol * 8];
            ulonglong2 a01 = *(const ulonglong2*)(arow);
            ulonglong2 a23 = *(const ulonglong2*)(arow + 4);
            ulonglong2 a45 = *(const ulonglong2*)(arow + 8);
            ulonglong2 a67 = *(const ulonglong2*)(arow + 12);
            ulonglong2 b01 = *(const ulonglong2*)(brow);
            ulonglong2 b23 = *(const ulonglong2*)(brow + 4);
            unsigned long long a2[8] = {a01.x, a01.y, a23.x, a23.y,
                                        a45.x, a45.y, a67.x, a67.y};
            unsigned long long b2[4] = {b01.x, b01.y, b23.x, b23.y};
#pragma unroll
            for (int i = 0; i < 8; i++)
#pragma unroll
                for (int j = 0; j < 4; j++) fma2(acc[i][j], a2[i], b2[j]);
        }
        if (t + 1 < nt) {
            const int q = (t + 1) & 1;
#pragma unroll
            for (int v = 0; v < 2; v++) {
                int idx = tid + v * 256;
                int r  = idx >> 2, kq = (idx & 3) << 2;
                *(float2*)(&As[q][kq + 0][2 * r]) = make_float2(pa[v].x, pa[v].x);
                *(float2*)(&As[q][kq + 1][2 * r]) = make_float2(pa[v].y, pa[v].y);
                *(float2*)(&As[q][kq + 2][2 * r]) = make_float2(pa[v].z, pa[v].z);
                *(float2*)(&As[q][kq + 3][2 * r]) = make_float2(pa[v].w, pa[v].w);
                int rb = idx >> 5, cb = (idx & 31) << 2;
                *(float4*)(&Bs[q][rb][cb]) = pb[v];
            }
        }
        __syncthreads();
    }

#pragma unroll
    for (int i = 0; i < 8; i++) {
        int r = row0 + trow * 8 + i;
#pragma unroll
        for (int j = 0; j < 4; j++) {
            int c = col0 + tcol * 8 + j * 2;
            if (c >= N) continue;
            float2 v = unpack2(acc[i][j]);
            if (epi == EPI_BIAS || epi == EPI_RES_BIAS ||
                epi == EPI_GELU_BIAS || epi == EPI_BIAS_POS) {
                v.x += bias[c]; v.y += bias[c + 1];
            }
            if (epi == EPI_BIAS_POS) {
                const float* p = extra + (long long)(r & (SEQ - 1)) * N;
                v.x += p[c]; v.y += p[c + 1];
            }
            if (epi == EPI_RES || epi == EPI_RES_BIAS) {
                const float* p = extra + (long long)r * N;
                v.x += p[c]; v.y += p[c + 1];
            }
            if (epi == EPI_GELU_BIAS) { v.x = gelu_f(v.x); v.y = gelu_f(v.y); }
            *(float2*)(C + (long long)r * N + c) = v;
        }
    }
}

// ---------------------------------------------------------------------------
// LayerNorm (row = 512)
// ---------------------------------------------------------------------------
__global__ void layernorm_k(const float* __restrict__ X, float* __restrict__ Y,
                            const float* __restrict__ gg, const float* __restrict__ bb)
{
    __shared__ float sm[16];
    const int row = blockIdx.x;
    const int t   = threadIdx.x;
    const float* x = X + (long long)row * DIMN;
    float v0 = x[t], v1 = x[t + 256];
    float s = v0 + v1;
    float q = v0 * v0 + v1 * v1;
#pragma unroll
    for (int off = 16; off; off >>= 1) {
        s += __shfl_xor_sync(0xffffffffu, s, off);
        q += __shfl_xor_sync(0xffffffffu, q, off);
    }
    if ((t & 31) == 0) { sm[t >> 5] = s; sm[8 + (t >> 5)] = q; }
    __syncthreads();
    float S = 0.f, Q = 0.f;
#pragma unroll
    for (int i = 0; i < 8; i++) { S += sm[i]; Q += sm[8 + i]; }
    float mu  = S * (1.0f / DIMN);
    float var = Q * (1.0f / DIMN) - mu * mu;
    float inv = 1.0f / sqrtf(var + 1e-5f);
    Y[(long long)row * DIMN + t]       = (v0 - mu) * inv * gg[t]       + bb[t];
    Y[(long long)row * DIMN + t + 256] = (v1 - mu) * inv * gg[t + 256] + bb[t + 256];
}

// ---------------------------------------------------------------------------
// Fused flash attention: per (bh, qtile of 64) — online softmax, no HBM scores
// grid (8, 128), block 256. Dynamic smem: 4 x 64x65 floats = 66560 B.
// ---------------------------------------------------------------------------
__global__ __launch_bounds__(256)
void fattn_k(const float* __restrict__ Q, const float* __restrict__ K,
             const float* __restrict__ V, float* __restrict__ O)
{
    extern __shared__ float smbuf[];
    float (*Qs)[65] = (float (*)[65])(smbuf);
    float (*Ks)[65] = (float (*)[65])(smbuf + 4160);
    float (*Vs)[65] = (float (*)[65])(smbuf + 8320);
    float (*Ps)[65] = (float (*)[65])(smbuf + 12480);

    const int qt = blockIdx.x, bh = blockIdx.y;
    const int b = bh >> 3, h = bh & 7;
    const int tid = threadIdx.x;
    const int ty = tid >> 4, tx = tid & 15;

    // load Q tile once
#pragma unroll
    for (int v = 0; v < 4; v++) {
        int idx = tid + v * 256;
        int r = idx >> 4, c = (idx & 15) << 2;
        float4 t = *(const float4*)(Q + (long long)(b * SEQ + qt * 64 + r) * DIMN + h * 64 + c);
        Qs[r][c] = t.x; Qs[r][c + 1] = t.y; Qs[r][c + 2] = t.z; Qs[r][c + 3] = t.w;
    }

    float m[4], l[4], o[4][4];
#pragma unroll
    for (int i = 0; i < 4; i++) {
        m[i] = -1e30f; l[i] = 0.f;
#pragma unroll
        for (int j = 0; j < 4; j++) o[i][j] = 0.f;
    }

    for (int kt = 0; kt < 8; kt++) {
        // load K, V tiles
#pragma unroll
        for (int v = 0; v < 4; v++) {
            int idx = tid + v * 256;
            int r = idx >> 4, c = (idx & 15) << 2;
            float4 tk = *(const float4*)(K + (long long)(b * SEQ + kt * 64 + r) * DIMN + h * 64 + c);
            Ks[r][c] = tk.x; Ks[r][c + 1] = tk.y; Ks[r][c + 2] = tk.z; Ks[r][c + 3] = tk.w;
            float4 tv = *(const float4*)(V + (long long)(b * SEQ + kt * 64 + r) * DIMN + h * 64 + c);
            Vs[r][c] = tv.x; Vs[r][c + 1] = tv.y; Vs[r][c + 2] = tv.z; Vs[r][c + 3] = tv.w;
        }
        __syncthreads();

        // S = Q K^T * 0.125
        float s[4][4] = {};
#pragma unroll 8
        for (int d = 0; d < 64; d++) {
            float qv[4], kv[4];
#pragma unroll
            for (int i = 0; i < 4; i++) qv[i] = Qs[ty * 4 + i][d];
#pragma unroll
            for (int j = 0; j < 4; j++) kv[j] = Ks[tx * 4 + j][d];
#pragma unroll
            for (int i = 0; i < 4; i++)
#pragma unroll
                for (int j = 0; j < 4; j++) s[i][j] += qv[i] * kv[j];
        }

        float p[4][4];
#pragma unroll
        for (int i = 0; i < 4; i++) {
            float rm = -1e30f;
#pragma unroll
            for (int j = 0; j < 4; j++) { s[i][j] *= 0.125f; rm = fmaxf(rm, s[i][j]); }
#pragma unroll
            for (int off = 8; off; off >>= 1)
                rm = fmaxf(rm, __shfl_xor_sync(0xffffffffu, rm, off));
            float mn = fmaxf(m[i], rm);
            float sc = __expf(m[i] - mn);
            float rs = 0.f;
#pragma unroll
            for (int j = 0; j < 4; j++) { p[i][j] = __expf(s[i][j] - mn); rs += p[i][j]; }
#pragma unroll
            for (int off = 8; off; off >>= 1)
                rs += __shfl_xor_sync(0xffffffffu, rs, off);
            l[i] = l[i] * sc + rs;
#pragma unroll
            for (int j = 0; j < 4; j++) o[i][j] *= sc;
            m[i] = mn;
        }

        // store P tile
#pragma unroll
        for (int i = 0; i < 4; i++)
#pragma unroll
            for (int j = 0; j < 4; j++) Ps[ty * 4 + i][tx * 4 + j] = p[i][j];
        __syncthreads();

        // O += P V
#pragma unroll 8
        for (int kk = 0; kk < 64; kk++) {
            float a[4], vv[4];
#pragma unroll
            for (int i = 0; i < 4; i++) a[i] = Ps[ty * 4 + i][kk];
#pragma unroll
            for (int j = 0; j < 4; j++) vv[j] = Vs[kk][tx * 4 + j];
#pragma unroll
            for (int i = 0; i < 4; i++)
#pragma unroll
                for (int j = 0; j < 4; j++) o[i][j] += a[i] * vv[j];
        }
        __syncthreads();
    }

#pragma unroll
    for (int i = 0; i < 4; i++) {
        int row = b * SEQ + qt * 64 + ty * 4 + i;
        float inv = 1.0f / l[i];
        float4 t = make_float4(o[i][0] * inv, o[i][1] * inv,
                               o[i][2] * inv, o[i][3] * inv);
        *(float4*)(O + (long long)row * DIMN + h * 64 + tx * 4) = t;
    }
}

// ---------------------------------------------------------------------------
// VQ
// ---------------------------------------------------------------------------
__global__ void cb_norm_k(const float* __restrict__ cb)
{
    int c = blockIdx.x * 256 + threadIdx.x;
    float s = 0.f;
    const float* p = cb + (long long)c * CBD;
#pragma unroll 8
    for (int d = 0; d < CBD; d++) { float v = p[d]; s += v * v; }
    g_cn[c] = 0.5f * s;
}

__global__ __launch_bounds__(256)
void vq_argmin_k(const float* __restrict__ Z, const float* __restrict__ cb)
{
    const int zb = blockIdx.x;          // 128 z-tiles of 64 rows
    const int sp = blockIdx.y;          // codebook split
    __shared__ float Zs[64][65];
    __shared__ float Cs[64][65];
    const int tid = threadIdx.x;
    const int ty = tid >> 4, tx = tid & 15;
#pragma unroll
    for (int v = 0; v < 4; v++) {
        int idx = tid + v * 256;
        int r = idx >> 4, c = (idx & 15) << 2;
        float4 t = *(const float4*)(Z + (long long)(zb * 64 + r) * CBD + c);
        Zs[r][c] = t.x; Zs[r][c + 1] = t.y; Zs[r][c + 2] = t.z; Zs[r][c + 3] = t.w;
    }
    __syncthreads();

    float bestv[4]; int bestc[4];
#pragma unroll
    for (int i = 0; i < 4; i++) { bestv[i] = -1e30f; bestc[i] = sp * (CBSZ / NSPLIT); }

    const int cbeg = sp * (CBSZ / NSPLIT);
    const int cend = cbeg + (CBSZ / NSPLIT);
    for (int c0 = cbeg; c0 < cend; c0 += 64) {
#pragma unroll
        for (int v = 0; v < 4; v++) {
            int idx = tid + v * 256;
            int r = idx >> 4, c = (idx & 15) << 2;
            float4 t = *(const float4*)(cb + (long long)(c0 + r) * CBD + c);
            Cs[r][c] = t.x; Cs[r][c + 1] = t.y; Cs[r][c + 2] = t.z; Cs[r][c + 3] = t.w;
        }
        __syncthreads();
        float acc[4][4] = {};
#pragma unroll 8
        for (int d = 0; d < 64; d++) {
            float zv[4], cv[4];
#pragma unroll
            for (int i = 0; i < 4; i++) zv[i] = Zs[ty * 4 + i][d];
#pragma unroll
            for (int j = 0; j < 4; j++) cv[j] = Cs[tx * 4 + j][d];
#pragma unroll
            for (int i = 0; i < 4; i++)
#pragma unroll
                for (int j = 0; j < 4; j++) acc[i][j] += zv[i] * cv[j];
        }
#pragma unroll
        for (int i = 0; i < 4; i++)
#pragma unroll
            for (int j = 0; j < 4; j++) {
                int c = c0 + tx * 4 + j;
                float scv = acc[i][j] - g_cn[c];
                if (scv > bestv[i] || (scv == bestv[i] && c < bestc[i])) {
                    bestv[i] = scv; bestc[i] = c;
                }
            }
        __syncthreads();
    }
#pragma unroll
    for (int i = 0; i < 4; i++) {
        float v = bestv[i]; int c = bestc[i];
#pragma unroll
        for (int off = 8; off; off >>= 1) {
            float ov = __shfl_xor_sync(0xffffffffu, v, off);
            int   oc = __shfl_xor_sync(0xffffffffu, c, off);
            if (ov > v || (ov == v && oc < c)) { v = ov; c = oc; }
        }
        if (tx == 0) {
            g_bv[sp][zb * 64 + ty * 4 + i] = v;
            g_bc[sp][zb * 64 + ty * 4 + i] = c;
        }
    }
}

__global__ void vq_combine_k()
{
    int t = blockIdx.x * 256 + threadIdx.x;
    float bv = g_bv[0][t]; int bc = g_bc[0][t];
#pragma unroll
    for (int s = 1; s < NSPLIT; s++) {
        float v = g_bv[s][t]; int c = g_bc[s][t];
        if (v > bv) { bv = v; bc = c; }
    }
    g_idx[t] = bc;
}

__global__ void vq_reduce_k(const float* __restrict__ cb,
                            const float* __restrict__ Z,
                            float* __restrict__ out)
{
    __shared__ float ssum[256];
    __shared__ float sloss[256];
    const int b = blockIdx.x;
    const int tid = threadIdx.x;
    const int d = tid & 63;
    const int sg = tid >> 6;
    float sum = 0.f, loss = 0.f;
    for (int s = sg; s < SEQ; s += 4) {
        int c = g_idx[b * SEQ + s];
        float qv = cb[(long long)c * CBD + d];
        float zv = Z[((long long)b * SEQ + s) * CBD + d];
        sum += qv;
        float dd = qv - zv;
        loss += dd * dd;
    }
    ssum[tid] = sum; sloss[tid] = loss;
    __syncthreads();
    if (tid < 64)
        out[b * CBD + tid] = ssum[tid] + ssum[tid + 64] + ssum[tid + 128] + ssum[tid + 192];
    for (int st = 128; st > 0; st >>= 1) {
        if (tid < st) sloss[tid] += sloss[tid + st];
        __syncthreads();
    }
    if (tid == 0) g_part[b] = sloss[0];
}

__global__ void vq_finish_k(float* __restrict__ out, int out_size)
{
    if (threadIdx.x == 0 && out_size > NBAT * CBD) {
        float s = 0.f;
        for (int i = 0; i < NBAT; i++) s += g_part[i];
        out[NBAT * CBD] = s / (float)(TOK * CBD);
    }
}

// ---------------------------------------------------------------------------
// Launch
// ---------------------------------------------------------------------------
extern "C" void kernel_launch(void* const* d_in, const int* in_sizes, int n_in,
                              void* d_out, int out_size)
{
    (void)in_sizes; (void)n_in;
    const float* x    = (const float*)d_in[0];
    const float* w_in = (const float*)d_in[1];
    const float* b_in = (const float*)d_in[2];
    const float* pos  = (const float*)d_in[3];
    const float* ln1g = (const float*)d_in[4];
    const float* ln1b = (const float*)d_in[5];
    const float* wq   = (const float*)d_in[6];
    const float* wk   = (const float*)d_in[7];
    const float* wv   = (const float*)d_in[8];
    const float* wo   = (const float*)d_in[9];
    const float* ln2g = (const float*)d_in[10];
    const float* ln2b = (const float*)d_in[11];
    const float* fw1  = (const float*)d_in[12];
    const float* fb1  = (const float*)d_in[13];
    const float* fw2  = (const float*)d_in[14];
    const float* fb2  = (const float*)d_in[15];
    const float* lnfg = (const float*)d_in[16];
    const float* lnfb = (const float*)d_in[17];
    const float* wout = (const float*)d_in[18];
    const float* bout = (const float*)d_in[19];
    const float* cbk  = (const float*)d_in[20];
    float* out = (float*)d_out;

    float *h, *ln, *qb, *kb, *vb, *att, *ff, *z;
    cudaGetSymbolAddress((void**)&h,   g_h);
    cudaGetSymbolAddress((void**)&ln,  g_lnb);
    cudaGetSymbolAddress((void**)&qb,  g_qb);
    cudaGetSymbolAddress((void**)&kb,  g_kb);
    cudaGetSymbolAddress((void**)&vb,  g_vb);
    cudaGetSymbolAddress((void**)&att, g_att);
    cudaGetSymbolAddress((void**)&ff,  g_ffb);
    cudaGetSymbolAddress((void**)&z,   g_z);

    static int smem_set = 0;
    if (!smem_set) {
        cudaFuncSetAttribute(fattn_k, cudaFuncAttributeMaxDynamicSharedMemorySize,
                             16640 * sizeof(float));
        smem_set = 1;
    }

    const dim3 g512(4, 64), g2048(16, 64), g64(1, 64);

    sgemm_k<<<g512, 256>>>(x, w_in, h, b_in, pos, DIMN, DIMN, EPI_BIAS_POS);

    for (int l = 0; l < 4; l++) {
        layernorm_k<<<TOK, 256>>>(h, ln, ln1g + l * DIMN, ln1b + l * DIMN);
        sgemm_k<<<g512, 256>>>(ln, wq + (long long)l * DIMN * DIMN, qb, nullptr, nullptr, DIMN, DIMN, EPI_NONE);
        sgemm_k<<<g512, 256>>>(ln, wk + (long long)l * DIMN * DIMN, kb, nullptr, nullptr, DIMN, DIMN, EPI_NONE);
        sgemm_k<<<g512, 256>>>(ln, wv + (long long)l * DIMN * DIMN, vb, nullptr, nullptr, DIMN, DIMN, EPI_NONE);
        fattn_k<<<dim3(8, NBAT * NHEAD), 256, 16640 * sizeof(float)>>>(qb, kb, vb, att);
        sgemm_k<<<g512, 256>>>(att, wo + (long long)l * DIMN * DIMN, h, nullptr, h, DIMN, DIMN, EPI_RES);
        layernorm_k<<<TOK, 256>>>(h, ln, ln2g + l * DIMN, ln2b + l * DIMN);
        sgemm_k<<<g2048, 256>>>(ln, fw1 + (long long)l * DIMN * FFD, ff, fb1 + l * FFD, nullptr, FFD, DIMN, EPI_GELU_BIAS);
        sgemm_k<<<g512, 256>>>(ff, fw2 + (long long)l * FFD * DIMN, h, fb2 + l * DIMN, h, DIMN, FFD, EPI_RES_BIAS);
    }

    layernorm_k<<<TOK, 256>>>(h, ln, lnfg, lnfb);
    sgemm_k<<<g64, 256>>>(ln, wout, z, bout, nullptr, CBD, DIMN, EPI_BIAS);

    cb_norm_k<<<CBSZ / 256, 256>>>(cbk);
    vq_argmin_k<<<dim3(TOK / 64, NSPLIT), 256>>>(z, cbk);
    vq_combine_k<<<TOK / 256, 256>>>();
    vq_reduce_k<<<NBAT, 256>>>(cbk, z, out);
    vq_finish_k<<<1, 32>>>(out, out_size);
}

// round 5
// speedup vs baseline: 1.5475x; 1.5475x over previous
#include <cuda_runtime.h>
#include <cstdint>

#define TOK   8192
#define DIMN  512
#define SEQ   512
#define NBAT  16
#define FFD   2048
#define CBSZ  8192
#define CBD   64
#define NSPLIT 4

__device__ float g_h  [TOK * DIMN];
__device__ float g_lnb[TOK * DIMN];
__device__ float g_qb [TOK * DIMN];
__device__ float g_kb [TOK * DIMN];
__device__ float g_vb [TOK * DIMN];
__device__ float g_att[TOK * DIMN];
__device__ float g_ffb[TOK * FFD];
__device__ float g_z  [TOK * CBD];
__device__ float g_cn [CBSZ];
__device__ float g_bv [NSPLIT][TOK];
__device__ int   g_bc [NSPLIT][TOK];
__device__ int   g_idx[TOK];
__device__ float g_part[NBAT];

enum { EPI_NONE = 0, EPI_BIAS = 1, EPI_BIAS_POS = 2, EPI_RES = 3,
       EPI_RES_BIAS = 4, EPI_GELU_BIAS = 5 };

__device__ __forceinline__ float gelu_f(float x) {
    float x3 = x * x * x;
    float t  = tanhf(0.7978845608028654f * (x + 0.044715f * x3));
    return 0.5f * x * (1.0f + t);
}

__device__ __forceinline__ float to_tf32(float x) {
    float r;
    asm("cvt.rna.tf32.f32 %0, %1;" : "=f"(r) : "f"(x));
    return r;
}

// m16n8k8 tf32 MMA, D += A*B (D==C in-place)
__device__ __forceinline__ void mma168(float* d, const uint32_t* a,
                                       uint32_t b0, uint32_t b1) {
    asm volatile(
        "mma.sync.aligned.m16n8k8.row.col.f32.tf32.tf32.f32 "
        "{%0,%1,%2,%3}, {%4,%5,%6,%7}, {%8,%9}, {%0,%1,%2,%3};"
        : "+f"(d[0]), "+f"(d[1]), "+f"(d[2]), "+f"(d[3])
        : "r"(a[0]), "r"(a[1]), "r"(a[2]), "r"(a[3]), "r"(b0), "r"(b1));
}

// ---------------------------------------------------------------------------
// tf32x3 GEMM via mma.sync: C[M,N] = A[M,K] @ B[K,N] (+epilogue).
// 128x128 CTA tile, BK=32, 8 warps each 32(m)x64(n).
// smem: Ab[128][36], As[128][36], Bb[32][136], Bs[32][136]  (71680 B dynamic)
// ---------------------------------------------------------------------------
#define TG_SMEM 71680

__global__ __launch_bounds__(256, 2)
void tgemm_k(const float* __restrict__ A, const float* __restrict__ B,
             float* __restrict__ C, const float* __restrict__ bias,
             const float* __restrict__ extra, int Nn, int K, int epi)
{
    extern __shared__ float sm[];
    float* Ab = sm;                          // [128][36]
    float* As = sm + 128 * 36;
    float* Bb = sm + 2 * 128 * 36;           // [32][136]
    float* Bs = sm + 2 * 128 * 36 + 32 * 136;

    const int tid  = threadIdx.x;
    const int lane = tid & 31;
    const int w    = tid >> 5;
    const int wm   = w & 3;                  // 4 m-warps
    const int wn   = w >> 2;                 // 2 n-warps
    const int row0 = blockIdx.y * 128;
    const int col0 = blockIdx.x * 128;
    const int m0w  = wm * 32;
    const int n0w  = wn * 64;
    const int g    = lane >> 2;              // 0..7
    const int tg   = lane & 3;               // 0..3

    float acc[2][8][4];
#pragma unroll
    for (int i = 0; i < 2; i++)
#pragma unroll
        for (int j = 0; j < 8; j++)
#pragma unroll
            for (int q = 0; q < 4; q++) acc[i][j][q] = 0.f;

    const int ar  = tid >> 3;                // A row (per v offset +32... computed per v)
    const int akq = (tid & 7) << 2;
    const int bk  = tid >> 5;
    const int bn  = (tid & 31) << 2;
    (void)ar;

    for (int c = 0; c < K; c += 32) {
        // gmem loads first (overlap previous compute)
        float4 pa[4], pb[4];
#pragma unroll
        for (int v = 0; v < 4; v++) {
            int idx = tid + (v << 8);
            int r   = idx >> 3;
            int kq  = (idx & 7) << 2;
            pa[v] = *(const float4*)(A + (long long)(row0 + r) * K + c + kq);
            int kr = idx >> 5;
            int nc = (idx & 31) << 2;
            pb[v] = make_float4(0.f, 0.f, 0.f, 0.f);
            if (col0 + nc < Nn)
                pb[v] = *(const float4*)(B + (long long)(c + kr) * Nn + col0 + nc);
        }
        __syncthreads();   // previous chunk's compute done before overwrite
#pragma unroll
        for (int v = 0; v < 4; v++) {
            int idx = tid + (v << 8);
            int r   = idx >> 3;
            int kq  = (idx & 7) << 2;
            float4 bg, smv;
            bg.x = to_tf32(pa[v].x); smv.x = to_tf32(pa[v].x - bg.x);
            bg.y = to_tf32(pa[v].y); smv.y = to_tf32(pa[v].y - bg.y);
            bg.z = to_tf32(pa[v].z); smv.z = to_tf32(pa[v].z - bg.z);
            bg.w = to_tf32(pa[v].w); smv.w = to_tf32(pa[v].w - bg.w);
            *(float4*)(Ab + r * 36 + kq) = bg;
            *(float4*)(As + r * 36 + kq) = smv;
            int kr = idx >> 5;
            int nc = (idx & 31) << 2;
            float4 bgb, smb;
            bgb.x = to_tf32(pb[v].x); smb.x = to_tf32(pb[v].x - bgb.x);
            bgb.y = to_tf32(pb[v].y); smb.y = to_tf32(pb[v].y - bgb.y);
            bgb.z = to_tf32(pb[v].z); smb.z = to_tf32(pb[v].z - bgb.z);
            bgb.w = to_tf32(pb[v].w); smb.w = to_tf32(pb[v].w - bgb.w);
            *(float4*)(Bb + kr * 136 + nc) = bgb;
            *(float4*)(Bs + kr * 136 + nc) = smb;
        }
        __syncthreads();

#pragma unroll
        for (int ks = 0; ks < 4; ks++) {
            const int kl = ks << 3;
            uint32_t fab[2][4], fas[2][4];
#pragma unroll
            for (int i = 0; i < 2; i++) {
                int rb = m0w + i * 16 + g;
                fab[i][0] = __float_as_uint(Ab[rb * 36 + kl + tg]);
                fab[i][1] = __float_as_uint(Ab[(rb + 8) * 36 + kl + tg]);
                fab[i][2] = __float_as_uint(Ab[rb * 36 + kl + tg + 4]);
                fab[i][3] = __float_as_uint(Ab[(rb + 8) * 36 + kl + tg + 4]);
                fas[i][0] = __float_as_uint(As[rb * 36 + kl + tg]);
                fas[i][1] = __float_as_uint(As[(rb + 8) * 36 + kl + tg]);
                fas[i][2] = __float_as_uint(As[rb * 36 + kl + tg + 4]);
                fas[i][3] = __float_as_uint(As[(rb + 8) * 36 + kl + tg + 4]);
            }
#pragma unroll
            for (int j = 0; j < 8; j++) {
                int nb = n0w + j * 8 + g;
                uint32_t bb0 = __float_as_uint(Bb[(kl + tg) * 136 + nb]);
                uint32_t bb1 = __float_as_uint(Bb[(kl + 4 + tg) * 136 + nb]);
                uint32_t bs0 = __float_as_uint(Bs[(kl + tg) * 136 + nb]);
                uint32_t bs1 = __float_as_uint(Bs[(kl + 4 + tg) * 136 + nb]);
#pragma unroll
                for (int i = 0; i < 2; i++) {
                    mma168(acc[i][j], fab[i], bb0, bb1);
                    mma168(acc[i][j], fab[i], bs0, bs1);
                    mma168(acc[i][j], fas[i], bb0, bb1);
                }
            }
        }
    }

    // ---- epilogue ----
#pragma unroll
    for (int i = 0; i < 2; i++) {
        int r = row0 + m0w + i * 16 + g;
#pragma unroll
        for (int j = 0; j < 8; j++) {
            int cc = col0 + n0w + j * 8 + 2 * tg;
            if (cc >= Nn) continue;
            float2 v0 = make_float2(acc[i][j][0], acc[i][j][1]);
            float2 v1 = make_float2(acc[i][j][2], acc[i][j][3]);
            if (epi == EPI_BIAS || epi == EPI_RES_BIAS ||
                epi == EPI_GELU_BIAS || epi == EPI_BIAS_POS) {
                float2 b2 = *(const float2*)(bias + cc);
                v0.x += b2.x; v0.y += b2.y;
                v1.x += b2.x; v1.y += b2.y;
            }
            if (epi == EPI_BIAS_POS) {
                float2 p0 = *(const float2*)(extra + (long long)(r & (SEQ - 1)) * Nn + cc);
                float2 p1 = *(const float2*)(extra + (long long)((r + 8) & (SEQ - 1)) * Nn + cc);
                v0.x += p0.x; v0.y += p0.y;
                v1.x += p1.x; v1.y += p1.y;
            }
            if (epi == EPI_RES || epi == EPI_RES_BIAS) {
                float2 e0 = *(const float2*)(extra + (long long)r * Nn + cc);
                float2 e1 = *(const float2*)(extra + (long long)(r + 8) * Nn + cc);
                v0.x += e0.x; v0.y += e0.y;
                v1.x += e1.x; v1.y += e1.y;
            }
            if (epi == EPI_GELU_BIAS) {
                v0.x = gelu_f(v0.x); v0.y = gelu_f(v0.y);
                v1.x = gelu_f(v1.x); v1.y = gelu_f(v1.y);
            }
            *(float2*)(C + (long long)r * Nn + cc) = v0;
            *(float2*)(C + (long long)(r + 8) * Nn + cc) = v1;
        }
    }
}

// ---------------------------------------------------------------------------
// LayerNorm (row = 512)
// ---------------------------------------------------------------------------
__global__ void layernorm_k(const float* __restrict__ X, float* __restrict__ Y,
                            const float* __restrict__ gg, const float* __restrict__ bb)
{
    __shared__ float sm[16];
    const int row = blockIdx.x;
    const int t   = threadIdx.x;
    const float* x = X + (long long)row * DIMN;
    float v0 = x[t], v1 = x[t + 256];
    float s = v0 + v1;
    float q = v0 * v0 + v1 * v1;
#pragma unroll
    for (int off = 16; off; off >>= 1) {
        s += __shfl_xor_sync(0xffffffffu, s, off);
        q += __shfl_xor_sync(0xffffffffu, q, off);
    }
    if ((t & 31) == 0) { sm[t >> 5] = s; sm[8 + (t >> 5)] = q; }
    __syncthreads();
    float S = 0.f, Q = 0.f;
#pragma unroll
    for (int i = 0; i < 8; i++) { S += sm[i]; Q += sm[8 + i]; }
    float mu  = S * (1.0f / DIMN);
    float var = Q * (1.0f / DIMN) - mu * mu;
    float inv = 1.0f / sqrtf(var + 1e-5f);
    Y[(long long)row * DIMN + t]       = (v0 - mu) * inv * gg[t]       + bb[t];
    Y[(long long)row * DIMN + t + 256] = (v1 - mu) * inv * gg[t + 256] + bb[t + 256];
}

// ---------------------------------------------------------------------------
// Fused flash attention (SIMT fp32) — from the passing R2 kernel
// ---------------------------------------------------------------------------
__global__ __launch_bounds__(256)
void fattn_k(const float* __restrict__ Q, const float* __restrict__ K,
             const float* __restrict__ V, float* __restrict__ O)
{
    extern __shared__ float smbuf[];
    float (*Qs)[65] = (float (*)[65])(smbuf);
    float (*Ks)[65] = (float (*)[65])(smbuf + 4160);
    float (*Vs)[65] = (float (*)[65])(smbuf + 8320);
    float (*Ps)[65] = (float (*)[65])(smbuf + 12480);

    const int qt = blockIdx.x, bh = blockIdx.y;
    const int b = bh >> 3, h = bh & 7;
    const int tid = threadIdx.x;
    const int ty = tid >> 4, tx = tid & 15;

#pragma unroll
    for (int v = 0; v < 4; v++) {
        int idx = tid + v * 256;
        int r = idx >> 4, c = (idx & 15) << 2;
        float4 t = *(const float4*)(Q + (long long)(b * SEQ + qt * 64 + r) * DIMN + h * 64 + c);
        Qs[r][c] = t.x; Qs[r][c + 1] = t.y; Qs[r][c + 2] = t.z; Qs[r][c + 3] = t.w;
    }

    float m[4], l[4], o[4][4];
#pragma unroll
    for (int i = 0; i < 4; i++) {
        m[i] = -1e30f; l[i] = 0.f;
#pragma unroll
        for (int j = 0; j < 4; j++) o[i][j] = 0.f;
    }

    for (int kt = 0; kt < 8; kt++) {
#pragma unroll
        for (int v = 0; v < 4; v++) {
            int idx = tid + v * 256;
            int r = idx >> 4, c = (idx & 15) << 2;
            float4 tk = *(const float4*)(K + (long long)(b * SEQ + kt * 64 + r) * DIMN + h * 64 + c);
            Ks[r][c] = tk.x; Ks[r][c + 1] = tk.y; Ks[r][c + 2] = tk.z; Ks[r][c + 3] = tk.w;
            float4 tv = *(const float4*)(V + (long long)(b * SEQ + kt * 64 + r) * DIMN + h * 64 + c);
            Vs[r][c] = tv.x; Vs[r][c + 1] = tv.y; Vs[r][c + 2] = tv.z; Vs[r][c + 3] = tv.w;
        }
        __syncthreads();

        float s[4][4] = {};
#pragma unroll 8
        for (int d = 0; d < 64; d++) {
            float qv[4], kv[4];
#pragma unroll
            for (int i = 0; i < 4; i++) qv[i] = Qs[ty * 4 + i][d];
#pragma unroll
            for (int j = 0; j < 4; j++) kv[j] = Ks[tx * 4 + j][d];
#pragma unroll
            for (int i = 0; i < 4; i++)
#pragma unroll
                for (int j = 0; j < 4; j++) s[i][j] += qv[i] * kv[j];
        }

        float p[4][4];
#pragma unroll
        for (int i = 0; i < 4; i++) {
            float rm = -1e30f;
#pragma unroll
            for (int j = 0; j < 4; j++) { s[i][j] *= 0.125f; rm = fmaxf(rm, s[i][j]); }
#pragma unroll
            for (int off = 8; off; off >>= 1)
                rm = fmaxf(rm, __shfl_xor_sync(0xffffffffu, rm, off));
            float mn = fmaxf(m[i], rm);
            float sc = __expf(m[i] - mn);
            float rs = 0.f;
#pragma unroll
            for (int j = 0; j < 4; j++) { p[i][j] = __expf(s[i][j] - mn); rs += p[i][j]; }
#pragma unroll
            for (int off = 8; off; off >>= 1)
                rs += __shfl_xor_sync(0xffffffffu, rs, off);
            l[i] = l[i] * sc + rs;
#pragma unroll
            for (int j = 0; j < 4; j++) o[i][j] *= sc;
            m[i] = mn;
        }

#pragma unroll
        for (int i = 0; i < 4; i++)
#pragma unroll
            for (int j = 0; j < 4; j++) Ps[ty * 4 + i][tx * 4 + j] = p[i][j];
        __syncthreads();

#pragma unroll 8
        for (int kk = 0; kk < 64; kk++) {
            float a[4], vv[4];
#pragma unroll
            for (int i = 0; i < 4; i++) a[i] = Ps[ty * 4 + i][kk];
#pragma unroll
            for (int j = 0; j < 4; j++) vv[j] = Vs[kk][tx * 4 + j];
#pragma unroll
            for (int i = 0; i < 4; i++)
#pragma unroll
                for (int j = 0; j < 4; j++) o[i][j] += a[i] * vv[j];
        }
        __syncthreads();
    }

#pragma unroll
    for (int i = 0; i < 4; i++) {
        int row = b * SEQ + qt * 64 + ty * 4 + i;
        float inv = 1.0f / l[i];
        float4 t = make_float4(o[i][0] * inv, o[i][1] * inv,
                               o[i][2] * inv, o[i][3] * inv);
        *(float4*)(O + (long long)row * DIMN + h * 64 + tx * 4) = t;
    }
}

// ---------------------------------------------------------------------------
// VQ
// ---------------------------------------------------------------------------
__global__ void cb_norm_k(const float* __restrict__ cb)
{
    int c = blockIdx.x * 256 + threadIdx.x;
    float s = 0.f;
    const float* p = cb + (long long)c * CBD;
#pragma unroll 8
    for (int d = 0; d < CBD; d++) { float v = p[d]; s += v * v; }
    g_cn[c] = 0.5f * s;
}

__global__ __launch_bounds__(256)
void vq_argmin_k(const float* __restrict__ Z, const float* __restrict__ cb)
{
    const int zb = blockIdx.x;
    const int sp = blockIdx.y;
    __shared__ float Zs[64][65];
    __shared__ float Cs[64][65];
    const int tid = threadIdx.x;
    const int ty = tid >> 4, tx = tid & 15;
#pragma unroll
    for (int v = 0; v < 4; v++) {
        int idx = tid + v * 256;
        int r = idx >> 4, c = (idx & 15) << 2;
        float4 t = *(const float4*)(Z + (long long)(zb * 64 + r) * CBD + c);
        Zs[r][c] = t.x; Zs[r][c + 1] = t.y; Zs[r][c + 2] = t.z; Zs[r][c + 3] = t.w;
    }
    __syncthreads();

    float bestv[4]; int bestc[4];
#pragma unroll
    for (int i = 0; i < 4; i++) { bestv[i] = -1e30f; bestc[i] = sp * (CBSZ / NSPLIT); }

    const int cbeg = sp * (CBSZ / NSPLIT);
    const int cend = cbeg + (CBSZ / NSPLIT);
    for (int c0 = cbeg; c0 < cend; c0 += 64) {
#pragma unroll
        for (int v = 0; v < 4; v++) {
            int idx = tid + v * 256;
            int r = idx >> 4, c = (idx & 15) << 2;
            float4 t = *(const float4*)(cb + (long long)(c0 + r) * CBD + c);
            Cs[r][c] = t.x; Cs[r][c + 1] = t.y; Cs[r][c + 2] = t.z; Cs[r][c + 3] = t.w;
        }
        __syncthreads();
        float acc[4][4] = {};
#pragma unroll 8
        for (int d = 0; d < 64; d++) {
            float zv[4], cv[4];
#pragma unroll
            for (int i = 0; i < 4; i++) zv[i] = Zs[ty * 4 + i][d];
#pragma unroll
            for (int j = 0; j < 4; j++) cv[j] = Cs[tx * 4 + j][d];
#pragma unroll
            for (int i = 0; i < 4; i++)
#pragma unroll
                for (int j = 0; j < 4; j++) acc[i][j] += zv[i] * cv[j];
        }
#pragma unroll
        for (int i = 0; i < 4; i++)
#pragma unroll
            for (int j = 0; j < 4; j++) {
                int c = c0 + tx * 4 + j;
                float scv = acc[i][j] - g_cn[c];
                if (scv > bestv[i] || (scv == bestv[i] && c < bestc[i])) {
                    bestv[i] = scv; bestc[i] = c;
                }
            }
        __syncthreads();
    }
#pragma unroll
    for (int i = 0; i < 4; i++) {
        float v = bestv[i]; int c = bestc[i];
#pragma unroll
        for (int off = 8; off; off >>= 1) {
            float ov = __shfl_xor_sync(0xffffffffu, v, off);
            int   oc = __shfl_xor_sync(0xffffffffu, c, off);
            if (ov > v || (ov == v && oc < c)) { v = ov; c = oc; }
        }
        if (tx == 0) {
            g_bv[sp][zb * 64 + ty * 4 + i] = v;
            g_bc[sp][zb * 64 + ty * 4 + i] = c;
        }
    }
}

__global__ void vq_combine_k()
{
    int t = blockIdx.x * 256 + threadIdx.x;
    float bv = g_bv[0][t]; int bc = g_bc[0][t];
#pragma unroll
    for (int s = 1; s < NSPLIT; s++) {
        float v = g_bv[s][t]; int c = g_bc[s][t];
        if (v > bv) { bv = v; bc = c; }
    }
    g_idx[t] = bc;
}

__global__ void vq_reduce_k(const float* __restrict__ cb,
                            const float* __restrict__ Z,
                            float* __restrict__ out)
{
    __shared__ float ssum[256];
    __shared__ float sloss[256];
    const int b = blockIdx.x;
    const int tid = threadIdx.x;
    const int d = tid & 63;
    const int sg = tid >> 6;
    float sum = 0.f, loss = 0.f;
    for (int s = sg; s < SEQ; s += 4) {
        int c = g_idx[b * SEQ + s];
        float qv = cb[(long long)c * CBD + d];
        float zv = Z[((long long)b * SEQ + s) * CBD + d];
        sum += qv;
        float dd = qv - zv;
        loss += dd * dd;
    }
    ssum[tid] = sum; sloss[tid] = loss;
    __syncthreads();
    if (tid < 64)
        out[b * CBD + tid] = ssum[tid] + ssum[tid + 64] + ssum[tid + 128] + ssum[tid + 192];
    for (int st = 128; st > 0; st >>= 1) {
        if (tid < st) sloss[tid] += sloss[tid + st];
        __syncthreads();
    }
    if (tid == 0) g_part[b] = sloss[0];
}

__global__ void vq_finish_k(float* __restrict__ out, int out_size)
{
    if (threadIdx.x == 0 && out_size > NBAT * CBD) {
        float s = 0.f;
        for (int i = 0; i < NBAT; i++) s += g_part[i];
        out[NBAT * CBD] = s / (float)(TOK * CBD);
    }
}

// ---------------------------------------------------------------------------
// Launch
// ---------------------------------------------------------------------------
extern "C" void kernel_launch(void* const* d_in, const int* in_sizes, int n_in,
                              void* d_out, int out_size)
{
    (void)in_sizes; (void)n_in;
    const float* x    = (const float*)d_in[0];
    const float* w_in = (const float*)d_in[1];
    const float* b_in = (const float*)d_in[2];
    const float* pos  = (const float*)d_in[3];
    const float* ln1g = (const float*)d_in[4];
    const float* ln1b = (const float*)d_in[5];
    const float* wq   = (const float*)d_in[6];
    const float* wk   = (const float*)d_in[7];
    const float* wv   = (const float*)d_in[8];
    const float* wo   = (const float*)d_in[9];
    const float* ln2g = (const float*)d_in[10];
    const float* ln2b = (const float*)d_in[11];
    const float* fw1  = (const float*)d_in[12];
    const float* fb1  = (const float*)d_in[13];
    const float* fw2  = (const float*)d_in[14];
    const float* fb2  = (const float*)d_in[15];
    const float* lnfg = (const float*)d_in[16];
    const float* lnfb = (const float*)d_in[17];
    const float* wout = (const float*)d_in[18];
    const float* bout = (const float*)d_in[19];
    const float* cbk  = (const float*)d_in[20];
    float* out = (float*)d_out;

    float *h, *ln, *qb, *kb, *vb, *att, *ff, *z;
    cudaGetSymbolAddress((void**)&h,   g_h);
    cudaGetSymbolAddress((void**)&ln,  g_lnb);
    cudaGetSymbolAddress((void**)&qb,  g_qb);
    cudaGetSymbolAddress((void**)&kb,  g_kb);
    cudaGetSymbolAddress((void**)&vb,  g_vb);
    cudaGetSymbolAddress((void**)&att, g_att);
    cudaGetSymbolAddress((void**)&ff,  g_ffb);
    cudaGetSymbolAddress((void**)&z,   g_z);

    cudaFuncSetAttribute(tgemm_k, cudaFuncAttributeMaxDynamicSharedMemorySize, TG_SMEM);
    cudaFuncSetAttribute(fattn_k, cudaFuncAttributeMaxDynamicSharedMemorySize,
                         16640 * (int)sizeof(float));

    const dim3 g512(4, 64), g2048(16, 64), g64(1, 64);

    tgemm_k<<<g512, 256, TG_SMEM>>>(x, w_in, h, b_in, pos, DIMN, DIMN, EPI_BIAS_POS);

    for (int l = 0; l < 4; l++) {
        layernorm_k<<<TOK, 256>>>(h, ln, ln1g + l * DIMN, ln1b + l * DIMN);
        tgemm_k<<<g512, 256, TG_SMEM>>>(ln, wq + (long long)l * DIMN * DIMN, qb, nullptr, nullptr, DIMN, DIMN, EPI_NONE);
        tgemm_k<<<g512, 256, TG_SMEM>>>(ln, wk + (long long)l * DIMN * DIMN, kb, nullptr, nullptr, DIMN, DIMN, EPI_NONE);
        tgemm_k<<<g512, 256, TG_SMEM>>>(ln, wv + (long long)l * DIMN * DIMN, vb, nullptr, nullptr, DIMN, DIMN, EPI_NONE);
        fattn_k<<<dim3(8, 128), 256, 16640 * sizeof(float)>>>(qb, kb, vb, att);
        tgemm_k<<<g512, 256, TG_SMEM>>>(att, wo + (long long)l * DIMN * DIMN, h, nullptr, h, DIMN, DIMN, EPI_RES);
        layernorm_k<<<TOK, 256>>>(h, ln, ln2g + l * DIMN, ln2b + l * DIMN);
        tgemm_k<<<g2048, 256, TG_SMEM>>>(ln, fw1 + (long long)l * DIMN * FFD, ff, fb1 + l * FFD, nullptr, FFD, DIMN, EPI_GELU_BIAS);
        tgemm_k<<<g512, 256, TG_SMEM>>>(ff, fw2 + (long long)l * FFD * DIMN, h, fb2 + l * DIMN, h, DIMN, FFD, EPI_RES_BIAS);
    }

    layernorm_k<<<TOK, 256>>>(h, ln, lnfg, lnfb);
    tgemm_k<<<g64, 256, TG_SMEM>>>(ln, wout, z, bout, nullptr, CBD, DIMN, EPI_BIAS);

    cb_norm_k<<<CBSZ / 256, 256>>>(cbk);
    vq_argmin_k<<<dim3(TOK / 64, NSPLIT), 256>>>(z, cbk);
    vq_combine_k<<<TOK / 256, 256>>>();
    vq_reduce_k<<<NBAT, 256>>>(cbk, z, out);
    vq_finish_k<<<1, 32>>>(out, out_size);
}